// round 3
// baseline (speedup 1.0000x reference)
#include <cuda_runtime.h>
#include <cuda_bf16.h>
#include <math.h>

#define B_  32
#define T_  64
#define S_  64
#define V_  32000
#define E_  512
#define H_  512
#define SD_ 1024
#define SCALE_ 0.04419417382415922f  // 1/sqrt(512)

__device__ float g_h[2][B_ * H_];
__device__ float g_c[B_ * H_];
__device__ float g_hhat[B_ * H_];
__device__ float g_keyp[B_ * SD_];
__device__ float g_ct[B_ * SD_];
__device__ float g_outs[T_ * B_ * H_];   // [t][b][h]

__device__ __forceinline__ float sigmoidf_(float x) {
    return 1.0f / (1.0f + __expf(-x));
}

__global__ void init_kernel(const float* __restrict__ hinit,
                            const float* __restrict__ iff) {
    int idx = blockIdx.x * blockDim.x + threadIdx.x;
    if (idx < B_ * H_) {
        int m = idx & (H_ - 1);
        g_h[0][idx] = hinit[m];
        g_c[idx]    = hinit[H_ + m];
        g_hhat[idx] = iff[m];
    }
}

// ---- LSTM gates + cell update. 256 blocks x 256 thr.
// Warp w -> column j = (w&3)*H + blockIdx.x*2 + (w>>2). 4-batch ILP.
__global__ void __launch_bounds__(256) lstm_kernel(
    const int* __restrict__ trg, const float* __restrict__ emb,
    const float* __restrict__ W_ih, const float* __restrict__ b_ih,
    const float* __restrict__ W_hh, const float* __restrict__ b_hh, int t)
{
    __shared__ float gs[8][B_];
    __shared__ int tok[B_];
    const int w = threadIdx.x >> 5, lane = threadIdx.x & 31;
    const int m = blockIdx.x * 2 + (w >> 2);
    const int j = (w & 3) * H_ + m;
    const int hb = t & 1;
    const float* __restrict__ h_in = g_h[hb];
    float* __restrict__ h_out = g_h[hb ^ 1];

    if (threadIdx.x < B_) tok[threadIdx.x] = trg[threadIdx.x * T_ + t];
    __syncthreads();

    const float4* Wi = (const float4*)(W_ih + (size_t)j * (E_ + H_));
    const float4* Wh = (const float4*)(W_hh + (size_t)j * H_);
    const float bias = b_ih[j] + b_hh[j];

    for (int b0 = 0; b0 < B_; b0 += 4) {
        const float4 *xe[4], *hh[4], *hp[4];
        #pragma unroll
        for (int u = 0; u < 4; ++u) {
            xe[u] = (const float4*)(emb + (size_t)tok[b0 + u] * E_);
            hh[u] = (const float4*)(g_hhat + (b0 + u) * H_);
            hp[u] = (const float4*)(h_in + (b0 + u) * H_);
        }
        float acc[4] = {0.f, 0.f, 0.f, 0.f};
        for (int i = lane; i < E_ / 4; i += 32) {
            float4 ww = Wi[i];
            #pragma unroll
            for (int u = 0; u < 4; ++u) {
                float4 a = xe[u][i];
                acc[u] += a.x * ww.x + a.y * ww.y + a.z * ww.z + a.w * ww.w;
            }
        }
        for (int i = lane; i < H_ / 4; i += 32) {
            float4 ww = Wi[E_ / 4 + i];
            #pragma unroll
            for (int u = 0; u < 4; ++u) {
                float4 a = hh[u][i];
                acc[u] += a.x * ww.x + a.y * ww.y + a.z * ww.z + a.w * ww.w;
            }
        }
        for (int i = lane; i < H_ / 4; i += 32) {
            float4 ww = Wh[i];
            #pragma unroll
            for (int u = 0; u < 4; ++u) {
                float4 a = hp[u][i];
                acc[u] += a.x * ww.x + a.y * ww.y + a.z * ww.z + a.w * ww.w;
            }
        }
        #pragma unroll
        for (int o = 16; o; o >>= 1) {
            #pragma unroll
            for (int u = 0; u < 4; ++u)
                acc[u] += __shfl_xor_sync(0xFFFFFFFFu, acc[u], o);
        }
        if (lane == 0) {
            #pragma unroll
            for (int u = 0; u < 4; ++u) gs[w][b0 + u] = acc[u] + bias;
        }
    }
    __syncthreads();

    if (threadIdx.x < 64) {
        int ml = threadIdx.x >> 5;
        int b  = threadIdx.x & 31;
        int m2 = blockIdx.x * 2 + ml;
        float ig = sigmoidf_(gs[ml * 4 + 0][b]);
        float fg = sigmoidf_(gs[ml * 4 + 1][b]);
        float gg = tanhf    (gs[ml * 4 + 2][b]);
        float og = sigmoidf_(gs[ml * 4 + 3][b]);
        float cn = fg * g_c[b * H_ + m2] + ig * gg;
        g_c[b * H_ + m2] = cn;
        h_out[b * H_ + m2] = og * tanhf(cn);
    }
}

// ---- key_p = h @ Wp^T + bp. 128 blocks x 8 warps; 4-batch ILP.
__global__ void __launch_bounds__(256) keyp_kernel(
    const float* __restrict__ Wp, const float* __restrict__ bp, int t)
{
    const int w = threadIdx.x >> 5, lane = threadIdx.x & 31;
    const int j = blockIdx.x * 8 + w;
    const float* __restrict__ h = g_h[(t + 1) & 1];
    const float4* Wr = (const float4*)(Wp + (size_t)j * H_);
    const float bj = bp[j];
    for (int b0 = 0; b0 < B_; b0 += 4) {
        float acc[4] = {0.f, 0.f, 0.f, 0.f};
        for (int i = lane; i < H_ / 4; i += 32) {
            float4 ww = Wr[i];
            #pragma unroll
            for (int u = 0; u < 4; ++u) {
                float4 a = ((const float4*)(h + (b0 + u) * H_))[i];
                acc[u] += a.x * ww.x + a.y * ww.y + a.z * ww.z + a.w * ww.w;
            }
        }
        #pragma unroll
        for (int o = 16; o; o >>= 1) {
            #pragma unroll
            for (int u = 0; u < 4; ++u)
                acc[u] += __shfl_xor_sync(0xFFFFFFFFu, acc[u], o);
        }
        if (lane == 0) {
            #pragma unroll
            for (int u = 0; u < 4; ++u) g_keyp[(b0 + u) * SD_ + j] = acc[u] + bj;
        }
    }
}

// ---- attention. grid (32 batches, 4 SD-slices) x 256 thr.
// Scores computed redundantly per slice (src is L2-resident); context split.
__global__ void __launch_bounds__(256) attn_kernel(const float* __restrict__ src)
{
    const int b = blockIdx.x, slice = blockIdx.y;
    __shared__ float sc[S_];
    __shared__ float skp[SD_];
    const int w = threadIdx.x >> 5, lane = threadIdx.x & 31;

    for (int i = threadIdx.x; i < SD_; i += 256) skp[i] = g_keyp[b * SD_ + i];
    __syncthreads();

    const float4* kp4 = (const float4*)skp;
    for (int s = w; s < S_; s += 8) {
        const float4* sr = (const float4*)(src + ((size_t)b * S_ + s) * SD_);
        float acc = 0.f;
        for (int i = lane; i < SD_ / 4; i += 32) {
            float4 a = kp4[i], x = sr[i];
            acc += a.x * x.x + a.y * x.y + a.z * x.z + a.w * x.w;
        }
        #pragma unroll
        for (int o = 16; o; o >>= 1) acc += __shfl_xor_sync(0xFFFFFFFFu, acc, o);
        if (lane == 0) sc[s] = acc * SCALE_;
    }
    __syncthreads();

    if (w == 0) {
        float v0 = sc[lane], v1 = sc[lane + 32];
        float mx = fmaxf(v0, v1);
        #pragma unroll
        for (int o = 16; o; o >>= 1) mx = fmaxf(mx, __shfl_xor_sync(0xFFFFFFFFu, mx, o));
        float e0 = __expf(v0 - mx), e1 = __expf(v1 - mx);
        float sm = e0 + e1;
        #pragma unroll
        for (int o = 16; o; o >>= 1) sm += __shfl_xor_sync(0xFFFFFFFFu, sm, o);
        float inv = 1.0f / sm;
        sc[lane] = e0 * inv;
        sc[lane + 32] = e1 * inv;
    }
    __syncthreads();

    const int d = slice * 256 + threadIdx.x;
    float acc = 0.f;
    #pragma unroll 8
    for (int s = 0; s < S_; ++s)
        acc += sc[s] * src[((size_t)b * S_ + s) * SD_ + d];
    g_ct[b * SD_ + d] = acc;
}

// ---- h_hat = tanh([h, c_t] @ Wah^T + bah). 64 blocks x 8 warps; 4-batch ILP.
__global__ void __launch_bounds__(256) hhat_kernel(
    const float* __restrict__ Wah, const float* __restrict__ bah, int t)
{
    const int w = threadIdx.x >> 5, lane = threadIdx.x & 31;
    const int j = blockIdx.x * 8 + w;
    const float* __restrict__ h = g_h[(t + 1) & 1];
    const float4* Wr = (const float4*)(Wah + (size_t)j * (H_ + SD_));
    const float bj = bah[j];
    for (int b0 = 0; b0 < B_; b0 += 4) {
        float acc[4] = {0.f, 0.f, 0.f, 0.f};
        for (int i = lane; i < H_ / 4; i += 32) {
            float4 ww = Wr[i];
            #pragma unroll
            for (int u = 0; u < 4; ++u) {
                float4 a = ((const float4*)(h + (b0 + u) * H_))[i];
                acc[u] += a.x * ww.x + a.y * ww.y + a.z * ww.z + a.w * ww.w;
            }
        }
        for (int i = lane; i < SD_ / 4; i += 32) {
            float4 ww = Wr[H_ / 4 + i];
            #pragma unroll
            for (int u = 0; u < 4; ++u) {
                float4 a = ((const float4*)(g_ct + (b0 + u) * SD_))[i];
                acc[u] += a.x * ww.x + a.y * ww.y + a.z * ww.z + a.w * ww.w;
            }
        }
        #pragma unroll
        for (int o = 16; o; o >>= 1) {
            #pragma unroll
            for (int u = 0; u < 4; ++u)
                acc[u] += __shfl_xor_sync(0xFFFFFFFFu, acc[u], o);
        }
        if (lane == 0) {
            #pragma unroll
            for (int u = 0; u < 4; ++u) {
                float v = tanhf(acc[u] + bj);
                g_hhat[(b0 + u) * H_ + j] = v;
                g_outs[((size_t)t * B_ + b0 + u) * H_ + j] = v;
            }
        }
    }
}

// ---- final projection GEMM (unchanged, fp32 64x64 tile) ----
#define BM 64
#define BN 64
#define BK 16
__global__ void __launch_bounds__(256) gemm_kernel(
    const float* __restrict__ Wfc, const float* __restrict__ bfc,
    float* __restrict__ out)
{
    __shared__ float As[BK][BM + 4];
    __shared__ float Bs[BK][BN + 4];

    const int tid = threadIdx.x;
    const int tx = tid & 15, ty = tid >> 4;
    const int r0 = blockIdx.y * BM;
    const int v0 = blockIdx.x * BN;
    const int ld_row = tid >> 2;
    const int ld_k   = (tid & 3) * 4;

    const float* __restrict__ A = g_outs;
    float acc[4][4] = {};

    for (int k0 = 0; k0 < H_; k0 += BK) {
        float4 a  = *(const float4*)&A  [(size_t)(r0 + ld_row) * H_ + k0 + ld_k];
        float4 bb = *(const float4*)&Wfc[(size_t)(v0 + ld_row) * H_ + k0 + ld_k];
        As[ld_k + 0][ld_row] = a.x;  As[ld_k + 1][ld_row] = a.y;
        As[ld_k + 2][ld_row] = a.z;  As[ld_k + 3][ld_row] = a.w;
        Bs[ld_k + 0][ld_row] = bb.x; Bs[ld_k + 1][ld_row] = bb.y;
        Bs[ld_k + 2][ld_row] = bb.z; Bs[ld_k + 3][ld_row] = bb.w;
        __syncthreads();
        #pragma unroll
        for (int k = 0; k < BK; ++k) {
            float4 av = *(const float4*)&As[k][ty * 4];
            float4 bv = *(const float4*)&Bs[k][tx * 4];
            acc[0][0] += av.x * bv.x; acc[0][1] += av.x * bv.y;
            acc[0][2] += av.x * bv.z; acc[0][3] += av.x * bv.w;
            acc[1][0] += av.y * bv.x; acc[1][1] += av.y * bv.y;
            acc[1][2] += av.y * bv.z; acc[1][3] += av.y * bv.w;
            acc[2][0] += av.z * bv.x; acc[2][1] += av.z * bv.y;
            acc[2][2] += av.z * bv.z; acc[2][3] += av.z * bv.w;
            acc[3][0] += av.w * bv.x; acc[3][1] += av.w * bv.y;
            acc[3][2] += av.w * bv.z; acc[3][3] += av.w * bv.w;
        }
        __syncthreads();
    }

    const int v = v0 + tx * 4;
    float4 bias = *(const float4*)&bfc[v];
    #pragma unroll
    for (int i = 0; i < 4; ++i) {
        int r = r0 + ty * 4 + i;
        int tt = r >> 5;
        int bb2 = r & 31;
        size_t off = ((size_t)(bb2 * T_ + tt)) * V_ + v;
        float4 res;
        res.x = acc[i][0] + bias.x;
        res.y = acc[i][1] + bias.y;
        res.z = acc[i][2] + bias.z;
        res.w = acc[i][3] + bias.w;
        *(float4*)&out[off] = res;
    }
}

__global__ void tail_kernel(float* __restrict__ out) {
    size_t base = (size_t)B_ * T_ * V_;
    int idx = blockIdx.x * blockDim.x + threadIdx.x;
    if (idx < B_ * H_) {
        out[base + idx]               = g_h[0][idx];
        out[base + B_ * H_ + idx]     = g_c[idx];
        out[base + 2 * B_ * H_ + idx] = g_hhat[idx];
    }
}

extern "C" void kernel_launch(void* const* d_in, const int* in_sizes, int n_in,
                              void* d_out, int out_size) {
    const float* src    = (const float*)d_in[0];
    const int*   trg    = (const int*)  d_in[1];
    const float* emb    = (const float*)d_in[2];
    const float* W_ih   = (const float*)d_in[3];
    const float* b_ih   = (const float*)d_in[4];
    const float* W_hh   = (const float*)d_in[5];
    const float* b_hh   = (const float*)d_in[6];
    const float* Wp     = (const float*)d_in[7];
    const float* bp     = (const float*)d_in[8];
    const float* Wah    = (const float*)d_in[9];
    const float* bah    = (const float*)d_in[10];
    const float* Wfc    = (const float*)d_in[11];
    const float* bfc    = (const float*)d_in[12];
    const float* iff    = (const float*)d_in[13];
    const float* hinit  = (const float*)d_in[14];
    float* out = (float*)d_out;

    init_kernel<<<32, 512>>>(hinit, iff);

    for (int t = 0; t < T_; ++t) {
        lstm_kernel<<<256, 256>>>(trg, emb, W_ih, b_ih, W_hh, b_hh, t);
        keyp_kernel<<<128, 256>>>(Wp, bp, t);
        attn_kernel<<<dim3(32, 4), 256>>>(src);
        hhat_kernel<<<64, 256>>>(Wah, bah, t);
    }

    dim3 ggrid(V_ / BN, (T_ * B_) / BM);
    gemm_kernel<<<ggrid, 256>>>(Wfc, bfc, out);

    tail_kernel<<<32, 512>>>(out);
}

// round 4
// speedup vs baseline: 1.7883x; 1.7883x over previous
#include <cuda_runtime.h>
#include <cuda_bf16.h>
#include <math.h>

#define B_  32
#define T_  64
#define S_  64
#define V_  32000
#define E_  512
#define H_  512
#define SD_ 1024
#define SCALE_ 0.04419417382415922f  // 1/sqrt(512)

#define NB 148           // persistent grid: <= SM count, all co-resident
#define NT 256
#define NW (NB * 8)      // 1184 warps

__device__ float g_h[2][B_ * H_];
__device__ float g_c[B_ * H_];
__device__ float g_hhat[B_ * H_];
__device__ float g_keyp[B_ * SD_];
__device__ float g_ct[B_ * SD_];
__device__ float g_outs[T_ * B_ * H_];   // [t][b][h]
__device__ unsigned g_arrive;            // grid barrier counter (monotonic per launch)

__device__ __forceinline__ float sigmoidf_(float x) {
    return 1.0f / (1.0f + __expf(-x));
}

// Monotonic grid barrier: all NB blocks co-resident (grid == NB <= #SM).
__device__ __forceinline__ void grid_sync(unsigned target) {
    __syncthreads();
    if (threadIdx.x == 0) {
        __threadfence();
        atomicAdd(&g_arrive, 1u);
        unsigned v;
        do {
            asm volatile("ld.global.acquire.gpu.u32 %0, [%1];"
                         : "=r"(v) : "l"(&g_arrive));
        } while (v < target);
    }
    __syncthreads();
}

// ---------------- init: broadcast initial states + reset barrier ----------------
__global__ void init_kernel(const float* __restrict__ hinit,
                            const float* __restrict__ iff) {
    if (blockIdx.x == 0 && threadIdx.x == 0) g_arrive = 0u;
    int idx = blockIdx.x * blockDim.x + threadIdx.x;
    if (idx < B_ * H_) {
        int m = idx & (H_ - 1);
        g_h[0][idx] = hinit[m];
        g_c[idx]    = hinit[H_ + m];
        g_hhat[idx] = iff[m];
    }
}

// ================= persistent recurrence kernel =================
__global__ void __launch_bounds__(NT) step_kernel(
    const int* __restrict__ trg, const float* __restrict__ emb,
    const float* __restrict__ W_ih, const float* __restrict__ b_ih,
    const float* __restrict__ W_hh, const float* __restrict__ b_hh,
    const float* __restrict__ Wp,  const float* __restrict__ bp,
    const float* __restrict__ Wah, const float* __restrict__ bah,
    const float* __restrict__ src, float* __restrict__ out)
{
    __shared__ int   tok[B_];
    __shared__ float sc[S_];
    __shared__ float skp[SD_];

    const int w    = threadIdx.x >> 5;
    const int lane = threadIdx.x & 31;
    const int gw   = blockIdx.x * 8 + w;   // global warp id, 0..1183
    unsigned bar = 0;

    const float4* Wi4 = (const float4*)W_ih;  // row stride 256 float4 (K=1024)
    const float4* Wh4 = (const float4*)W_hh;  // row stride 128 float4 (K=512)
    const float4* E4  = (const float4*)emb;   // row stride 128 float4

    for (int t = 0; t < T_; ++t) {
        if (threadIdx.x < B_) tok[threadIdx.x] = trg[threadIdx.x * T_ + t];
        __syncthreads();

        const float* __restrict__ h_in  = g_h[t & 1];
        float*       __restrict__ h_out = g_h[(t & 1) ^ 1];
        const float4* Hi4 = (const float4*)h_in;
        const float4* HH4 = (const float4*)g_hhat;

        // ---- phase 1: LSTM gates (all 4) + cell update.
        // task = m*4 + bg; warp computes 4 gate-dots for hidden index m,
        // batches b0..b0+7. 2048 tasks.
        for (int task = gw; task < 2048; task += NW) {
            const int m  = task >> 2;
            const int b0 = (task & 3) << 3;
            int tk[8];
            #pragma unroll
            for (int u = 0; u < 8; ++u) tk[u] = tok[b0 + u];

            float acc[4][8];
            #pragma unroll
            for (int g = 0; g < 4; ++g)
                #pragma unroll
                for (int u = 0; u < 8; ++u) acc[g][u] = 0.f;

            // segment A: x = emb[tok], K 0..511  (W_ih cols 0..511)
            #pragma unroll
            for (int kk = 0; kk < 4; ++kk) {
                const int i = (kk << 5) + lane;
                float4 wv[4];
                #pragma unroll
                for (int g = 0; g < 4; ++g)
                    wv[g] = Wi4[(size_t)(g * H_ + m) * 256 + i];
                #pragma unroll
                for (int u = 0; u < 8; ++u) {
                    float4 xv = E4[(size_t)tk[u] * 128 + i];
                    #pragma unroll
                    for (int g = 0; g < 4; ++g)
                        acc[g][u] += xv.x*wv[g].x + xv.y*wv[g].y
                                   + xv.z*wv[g].z + xv.w*wv[g].w;
                }
            }
            // segment B: h_hat, K 512..1023 (W_ih cols 512..1023)
            #pragma unroll
            for (int kk = 0; kk < 4; ++kk) {
                const int i = (kk << 5) + lane;
                float4 wv[4];
                #pragma unroll
                for (int g = 0; g < 4; ++g)
                    wv[g] = Wi4[(size_t)(g * H_ + m) * 256 + 128 + i];
                #pragma unroll
                for (int u = 0; u < 8; ++u) {
                    float4 xv = HH4[(b0 + u) * 128 + i];
                    #pragma unroll
                    for (int g = 0; g < 4; ++g)
                        acc[g][u] += xv.x*wv[g].x + xv.y*wv[g].y
                                   + xv.z*wv[g].z + xv.w*wv[g].w;
                }
            }
            // segment C: h_prev via W_hh
            #pragma unroll
            for (int kk = 0; kk < 4; ++kk) {
                const int i = (kk << 5) + lane;
                float4 wv[4];
                #pragma unroll
                for (int g = 0; g < 4; ++g)
                    wv[g] = Wh4[(size_t)(g * H_ + m) * 128 + i];
                #pragma unroll
                for (int u = 0; u < 8; ++u) {
                    float4 xv = Hi4[(b0 + u) * 128 + i];
                    #pragma unroll
                    for (int g = 0; g < 4; ++g)
                        acc[g][u] += xv.x*wv[g].x + xv.y*wv[g].y
                                   + xv.z*wv[g].z + xv.w*wv[g].w;
                }
            }

            // butterfly reduce all 32 accumulators across lanes
            #pragma unroll
            for (int o = 16; o; o >>= 1)
                #pragma unroll
                for (int g = 0; g < 4; ++g)
                    #pragma unroll
                    for (int u = 0; u < 8; ++u)
                        acc[g][u] += __shfl_xor_sync(0xFFFFFFFFu, acc[g][u], o);

            if (lane < 8) {
                float vi = 0.f, vf = 0.f, vg = 0.f, vo = 0.f;
                #pragma unroll
                for (int u = 0; u < 8; ++u)
                    if (lane == u) { vi = acc[0][u]; vf = acc[1][u];
                                     vg = acc[2][u]; vo = acc[3][u]; }
                const int b = b0 + lane;
                float ig = sigmoidf_(vi + b_ih[m]          + b_hh[m]);
                float fg = sigmoidf_(vf + b_ih[H_ + m]     + b_hh[H_ + m]);
                float gg = tanhf    (vg + b_ih[2*H_ + m]   + b_hh[2*H_ + m]);
                float og = sigmoidf_(vo + b_ih[3*H_ + m]   + b_hh[3*H_ + m]);
                float cn = fg * g_c[b * H_ + m] + ig * gg;
                g_c[b * H_ + m] = cn;
                h_out[b * H_ + m] = og * tanhf(cn);
            }
        }
        grid_sync(++bar * NB);

        // ---- phase 2: key_p = h @ Wp^T + bp (1024 warp tasks)
        if (gw < SD_) {
            const int j = gw;
            const float4* Wr = (const float4*)(Wp + (size_t)j * H_);
            const float bj = bp[j];
            const float4* H4 = (const float4*)h_out;
            for (int b0 = 0; b0 < B_; b0 += 4) {
                float acc[4] = {0.f, 0.f, 0.f, 0.f};
                #pragma unroll
                for (int i = lane; i < H_ / 4; i += 32) {
                    float4 ww = Wr[i];
                    #pragma unroll
                    for (int u = 0; u < 4; ++u) {
                        float4 a = H4[(b0 + u) * 128 + i];
                        acc[u] += a.x*ww.x + a.y*ww.y + a.z*ww.z + a.w*ww.w;
                    }
                }
                #pragma unroll
                for (int o = 16; o; o >>= 1)
                    #pragma unroll
                    for (int u = 0; u < 4; ++u)
                        acc[u] += __shfl_xor_sync(0xFFFFFFFFu, acc[u], o);
                if (lane == 0) {
                    #pragma unroll
                    for (int u = 0; u < 4; ++u)
                        g_keyp[(b0 + u) * SD_ + j] = acc[u] + bj;
                }
            }
        }
        grid_sync(++bar * NB);

        // ---- phase 3: attention (block per batch; blocks 32..147 idle)
        if (blockIdx.x < B_) {
            const int b = blockIdx.x;
            for (int i = threadIdx.x; i < SD_; i += NT)
                skp[i] = g_keyp[b * SD_ + i];
            __syncthreads();
            const float4* kp4 = (const float4*)skp;
            for (int s = w; s < S_; s += 8) {
                const float4* sr = (const float4*)(src + ((size_t)b * S_ + s) * SD_);
                float a = 0.f;
                #pragma unroll
                for (int i = lane; i < SD_ / 4; i += 32) {
                    float4 kv = kp4[i], xv = sr[i];
                    a += kv.x*xv.x + kv.y*xv.y + kv.z*xv.z + kv.w*xv.w;
                }
                #pragma unroll
                for (int o = 16; o; o >>= 1) a += __shfl_xor_sync(0xFFFFFFFFu, a, o);
                if (lane == 0) sc[s] = a * SCALE_;
            }
            __syncthreads();
            if (w == 0) {
                float v0 = sc[lane], v1 = sc[lane + 32];
                float mx = fmaxf(v0, v1);
                #pragma unroll
                for (int o = 16; o; o >>= 1)
                    mx = fmaxf(mx, __shfl_xor_sync(0xFFFFFFFFu, mx, o));
                float e0 = __expf(v0 - mx), e1 = __expf(v1 - mx);
                float sm = e0 + e1;
                #pragma unroll
                for (int o = 16; o; o >>= 1) sm += __shfl_xor_sync(0xFFFFFFFFu, sm, o);
                float inv = 1.0f / sm;
                sc[lane] = e0 * inv;
                sc[lane + 32] = e1 * inv;
            }
            __syncthreads();
            for (int d = threadIdx.x; d < SD_; d += NT) {
                float a = 0.f;
                #pragma unroll 8
                for (int s = 0; s < S_; ++s)
                    a += sc[s] * src[((size_t)b * S_ + s) * SD_ + d];
                g_ct[b * SD_ + d] = a;
            }
        }
        grid_sync(++bar * NB);

        // ---- phase 4: h_hat = tanh([h, c_t] @ Wah^T + bah) (512 warp tasks)
        if (gw < H_) {
            const int j = gw;
            const float4* Wr = (const float4*)(Wah + (size_t)j * (H_ + SD_));
            const float bj = bah[j];
            const float4* H4 = (const float4*)h_out;
            const float4* C4 = (const float4*)g_ct;
            for (int b0 = 0; b0 < B_; b0 += 4) {
                float acc[4] = {0.f, 0.f, 0.f, 0.f};
                #pragma unroll
                for (int i = lane; i < H_ / 4; i += 32) {
                    float4 ww = Wr[i];
                    #pragma unroll
                    for (int u = 0; u < 4; ++u) {
                        float4 a = H4[(b0 + u) * 128 + i];
                        acc[u] += a.x*ww.x + a.y*ww.y + a.z*ww.z + a.w*ww.w;
                    }
                }
                #pragma unroll
                for (int i = lane; i < SD_ / 4; i += 32) {
                    float4 ww = Wr[H_ / 4 + i];
                    #pragma unroll
                    for (int u = 0; u < 4; ++u) {
                        float4 a = C4[(b0 + u) * 256 + i];
                        acc[u] += a.x*ww.x + a.y*ww.y + a.z*ww.z + a.w*ww.w;
                    }
                }
                #pragma unroll
                for (int o = 16; o; o >>= 1)
                    #pragma unroll
                    for (int u = 0; u < 4; ++u)
                        acc[u] += __shfl_xor_sync(0xFFFFFFFFu, acc[u], o);
                if (lane == 0) {
                    #pragma unroll
                    for (int u = 0; u < 4; ++u) {
                        float v = tanhf(acc[u] + bj);
                        g_hhat[(b0 + u) * H_ + j] = v;
                        g_outs[((size_t)t * B_ + b0 + u) * H_ + j] = v;
                    }
                }
            }
        }
        grid_sync(++bar * NB);
    }

    // tail: final h (in g_h[0] after 64 steps), c, h_hat
    size_t base = (size_t)B_ * T_ * V_;
    for (int idx = blockIdx.x * NT + threadIdx.x; idx < B_ * H_; idx += NB * NT) {
        out[base + idx]               = g_h[0][idx];
        out[base + B_ * H_ + idx]     = g_c[idx];
        out[base + 2 * B_ * H_ + idx] = g_hhat[idx];
    }
}

// ---------------- final projection GEMM (fp32 64x64 tile) ----------------
#define BM 64
#define BN 64
#define BK 16
__global__ void __launch_bounds__(256) gemm_kernel(
    const float* __restrict__ Wfc, const float* __restrict__ bfc,
    float* __restrict__ out)
{
    __shared__ float As[BK][BM + 4];
    __shared__ float Bs[BK][BN + 4];

    const int tid = threadIdx.x;
    const int tx = tid & 15, ty = tid >> 4;
    const int r0 = blockIdx.y * BM;
    const int v0 = blockIdx.x * BN;
    const int ld_row = tid >> 2;
    const int ld_k   = (tid & 3) * 4;

    const float* __restrict__ A = g_outs;
    float acc[4][4] = {};

    for (int k0 = 0; k0 < H_; k0 += BK) {
        float4 a  = *(const float4*)&A  [(size_t)(r0 + ld_row) * H_ + k0 + ld_k];
        float4 bb = *(const float4*)&Wfc[(size_t)(v0 + ld_row) * H_ + k0 + ld_k];
        As[ld_k + 0][ld_row] = a.x;  As[ld_k + 1][ld_row] = a.y;
        As[ld_k + 2][ld_row] = a.z;  As[ld_k + 3][ld_row] = a.w;
        Bs[ld_k + 0][ld_row] = bb.x; Bs[ld_k + 1][ld_row] = bb.y;
        Bs[ld_k + 2][ld_row] = bb.z; Bs[ld_k + 3][ld_row] = bb.w;
        __syncthreads();
        #pragma unroll
        for (int k = 0; k < BK; ++k) {
            float4 av = *(const float4*)&As[k][ty * 4];
            float4 bv = *(const float4*)&Bs[k][tx * 4];
            acc[0][0] += av.x * bv.x; acc[0][1] += av.x * bv.y;
            acc[0][2] += av.x * bv.z; acc[0][3] += av.x * bv.w;
            acc[1][0] += av.y * bv.x; acc[1][1] += av.y * bv.y;
            acc[1][2] += av.y * bv.z; acc[1][3] += av.y * bv.w;
            acc[2][0] += av.z * bv.x; acc[2][1] += av.z * bv.y;
            acc[2][2] += av.z * bv.z; acc[2][3] += av.z * bv.w;
            acc[3][0] += av.w * bv.x; acc[3][1] += av.w * bv.y;
            acc[3][2] += av.w * bv.z; acc[3][3] += av.w * bv.w;
        }
        __syncthreads();
    }

    const int v = v0 + tx * 4;
    float4 bias = *(const float4*)&bfc[v];
    #pragma unroll
    for (int i = 0; i < 4; ++i) {
        int r = r0 + ty * 4 + i;
        int tt = r >> 5;
        int bb2 = r & 31;
        size_t off = ((size_t)(bb2 * T_ + tt)) * V_ + v;
        float4 res;
        res.x = acc[i][0] + bias.x;
        res.y = acc[i][1] + bias.y;
        res.z = acc[i][2] + bias.z;
        res.w = acc[i][3] + bias.w;
        *(float4*)&out[off] = res;
    }
}

extern "C" void kernel_launch(void* const* d_in, const int* in_sizes, int n_in,
                              void* d_out, int out_size) {
    const float* src    = (const float*)d_in[0];
    const int*   trg    = (const int*)  d_in[1];
    const float* emb    = (const float*)d_in[2];
    const float* W_ih   = (const float*)d_in[3];
    const float* b_ih   = (const float*)d_in[4];
    const float* W_hh   = (const float*)d_in[5];
    const float* b_hh   = (const float*)d_in[6];
    const float* Wp     = (const float*)d_in[7];
    const float* bp     = (const float*)d_in[8];
    const float* Wah    = (const float*)d_in[9];
    const float* bah    = (const float*)d_in[10];
    const float* Wfc    = (const float*)d_in[11];
    const float* bfc    = (const float*)d_in[12];
    const float* iff    = (const float*)d_in[13];
    const float* hinit  = (const float*)d_in[14];
    float* out = (float*)d_out;

    init_kernel<<<32, 512>>>(hinit, iff);

    step_kernel<<<NB, NT>>>(trg, emb, W_ih, b_ih, W_hh, b_hh,
                            Wp, bp, Wah, bah, src, out);

    dim3 ggrid(V_ / BN, (T_ * B_) / BM);
    gemm_kernel<<<ggrid, 256>>>(Wfc, bfc, out);
}

// round 5
// speedup vs baseline: 2.3998x; 1.3419x over previous
#include <cuda_runtime.h>
#include <cuda_bf16.h>
#include <math.h>

#define B_  32
#define T_  64
#define S_  64
#define V_  32000
#define E_  512
#define H_  512
#define SD_ 1024
#define SCALE_ 0.04419417382415922f  // 1/sqrt(512)

#define NB 148
#define NT 256
#define NW (NB * 8)

__device__ float g_h[2][B_ * H_];
__device__ float g_c[B_ * H_];
__device__ float g_hhat[B_ * H_];
__device__ float g_outs[T_ * B_ * H_];   // [t][b][h]
__device__ float g_Q[B_ * S_ * H_];      // Q[r][k] = sum_j src[r][j] * Wp[j][k]
__device__ float g_GT[H_ * B_ * S_];     // GT[j][r] = Wah2[j] . src[r]
__device__ float g_qb[B_ * S_];          // bp . src[r]
__device__ float g_sc[B_ * S_];          // scaled scores per step
__device__ unsigned g_arrive;

__device__ __forceinline__ float sigmoidf_(float x) {
    return 1.0f / (1.0f + __expf(-x));
}

__device__ __forceinline__ void grid_sync(unsigned target) {
    __syncthreads();
    if (threadIdx.x == 0) {
        __threadfence();
        atomicAdd(&g_arrive, 1u);
        unsigned v;
        do {
            asm volatile("ld.global.acquire.gpu.u32 %0, [%1];"
                         : "=r"(v) : "l"(&g_arrive));
        } while (v < target);
    }
    __syncthreads();
}

// ---------------- init ----------------
__global__ void init_kernel(const float* __restrict__ hinit,
                            const float* __restrict__ iff) {
    if (blockIdx.x == 0 && threadIdx.x == 0) g_arrive = 0u;
    int idx = blockIdx.x * blockDim.x + threadIdx.x;
    if (idx < B_ * H_) {
        int m = idx & (H_ - 1);
        g_h[0][idx] = hinit[m];
        g_c[idx]    = hinit[H_ + m];
        g_hhat[idx] = iff[m];
    }
}

// ---------------- qb[r] = bp . src[r] ----------------
__global__ void __launch_bounds__(256) qb_kernel(
    const float* __restrict__ src, const float* __restrict__ bp)
{
    const int w = threadIdx.x >> 5, lane = threadIdx.x & 31;
    const int r = blockIdx.x * 8 + w;   // 256 blocks -> 2048 warps
    const float4* sr = (const float4*)(src + (size_t)r * SD_);
    const float4* bv = (const float4*)bp;
    float a = 0.f;
    #pragma unroll
    for (int i = lane; i < SD_ / 4; i += 32) {
        float4 x = sr[i], b = bv[i];
        a += x.x*b.x + x.y*b.y + x.z*b.z + x.w*b.w;
    }
    #pragma unroll
    for (int o = 16; o; o >>= 1) a += __shfl_xor_sync(0xFFFFFFFFu, a, o);
    if (lane == 0) g_qb[r] = a;
}

// ---------------- Q = src(2048x1024) @ Wp(1024x512), NN GEMM ----------------
#define PBM 64
#define PBN 64
#define PBK 16
__global__ void __launch_bounds__(256) qgemm_kernel(
    const float* __restrict__ src, const float* __restrict__ Wp)
{
    __shared__ float As[PBK][PBM + 4];
    __shared__ float Bs[PBK][PBN + 4];
    const int tid = threadIdx.x;
    const int tx = tid & 15, ty = tid >> 4;
    const int r0 = blockIdx.y * PBM;
    const int v0 = blockIdx.x * PBN;
    const int a_row = tid >> 2, a_k = (tid & 3) * 4;
    const int b_k = tid >> 4, b_n = (tid & 15) * 4;

    float acc[4][4] = {};
    for (int k0 = 0; k0 < SD_; k0 += PBK) {
        float4 a = *(const float4*)&src[(size_t)(r0 + a_row) * SD_ + k0 + a_k];
        As[a_k + 0][a_row] = a.x; As[a_k + 1][a_row] = a.y;
        As[a_k + 2][a_row] = a.z; As[a_k + 3][a_row] = a.w;
        *(float4*)&Bs[b_k][b_n] =
            *(const float4*)&Wp[(size_t)(k0 + b_k) * H_ + v0 + b_n];
        __syncthreads();
        #pragma unroll
        for (int k = 0; k < PBK; ++k) {
            float4 av = *(const float4*)&As[k][ty * 4];
            float4 bv = *(const float4*)&Bs[k][tx * 4];
            acc[0][0]+=av.x*bv.x; acc[0][1]+=av.x*bv.y; acc[0][2]+=av.x*bv.z; acc[0][3]+=av.x*bv.w;
            acc[1][0]+=av.y*bv.x; acc[1][1]+=av.y*bv.y; acc[1][2]+=av.y*bv.z; acc[1][3]+=av.y*bv.w;
            acc[2][0]+=av.z*bv.x; acc[2][1]+=av.z*bv.y; acc[2][2]+=av.z*bv.z; acc[2][3]+=av.z*bv.w;
            acc[3][0]+=av.w*bv.x; acc[3][1]+=av.w*bv.y; acc[3][2]+=av.w*bv.z; acc[3][3]+=av.w*bv.w;
        }
        __syncthreads();
    }
    #pragma unroll
    for (int i = 0; i < 4; ++i) {
        float4 res = make_float4(acc[i][0], acc[i][1], acc[i][2], acc[i][3]);
        *(float4*)&g_Q[(size_t)(r0 + ty * 4 + i) * H_ + v0 + tx * 4] = res;
    }
}

// ---------------- GT[j][r] = Wah[j,512:1536] . src[r], NT GEMM ----------------
__global__ void __launch_bounds__(256) gtgemm_kernel(
    const float* __restrict__ Wah, const float* __restrict__ src)
{
    __shared__ float As[PBK][PBM + 4];   // j dim
    __shared__ float Bs[PBK][PBN + 4];   // r dim
    const int tid = threadIdx.x;
    const int tx = tid & 15, ty = tid >> 4;
    const int j0 = blockIdx.y * PBM;
    const int r0 = blockIdx.x * PBN;
    const int ld_row = tid >> 2, ld_k = (tid & 3) * 4;

    float acc[4][4] = {};
    for (int k0 = 0; k0 < SD_; k0 += PBK) {
        float4 a = *(const float4*)&Wah[(size_t)(j0 + ld_row) * (H_ + SD_) + H_ + k0 + ld_k];
        float4 b = *(const float4*)&src[(size_t)(r0 + ld_row) * SD_ + k0 + ld_k];
        As[ld_k + 0][ld_row] = a.x; As[ld_k + 1][ld_row] = a.y;
        As[ld_k + 2][ld_row] = a.z; As[ld_k + 3][ld_row] = a.w;
        Bs[ld_k + 0][ld_row] = b.x; Bs[ld_k + 1][ld_row] = b.y;
        Bs[ld_k + 2][ld_row] = b.z; Bs[ld_k + 3][ld_row] = b.w;
        __syncthreads();
        #pragma unroll
        for (int k = 0; k < PBK; ++k) {
            float4 av = *(const float4*)&As[k][ty * 4];
            float4 bv = *(const float4*)&Bs[k][tx * 4];
            acc[0][0]+=av.x*bv.x; acc[0][1]+=av.x*bv.y; acc[0][2]+=av.x*bv.z; acc[0][3]+=av.x*bv.w;
            acc[1][0]+=av.y*bv.x; acc[1][1]+=av.y*bv.y; acc[1][2]+=av.y*bv.z; acc[1][3]+=av.y*bv.w;
            acc[2][0]+=av.z*bv.x; acc[2][1]+=av.z*bv.y; acc[2][2]+=av.z*bv.z; acc[2][3]+=av.z*bv.w;
            acc[3][0]+=av.w*bv.x; acc[3][1]+=av.w*bv.y; acc[3][2]+=av.w*bv.z; acc[3][3]+=av.w*bv.w;
        }
        __syncthreads();
    }
    #pragma unroll
    for (int i = 0; i < 4; ++i) {
        float4 res = make_float4(acc[i][0], acc[i][1], acc[i][2], acc[i][3]);
        *(float4*)&g_GT[(size_t)(j0 + ty * 4 + i) * (B_ * S_) + r0 + tx * 4] = res;
    }
}

// ================= persistent recurrence kernel =================
__global__ void __launch_bounds__(NT) step_kernel(
    const int* __restrict__ trg, const float* __restrict__ emb,
    const float* __restrict__ W_ih, const float* __restrict__ b_ih,
    const float* __restrict__ W_hh, const float* __restrict__ b_hh,
    const float* __restrict__ Wah, const float* __restrict__ bah,
    float* __restrict__ out)
{
    __shared__ int   tok[B_];
    __shared__ float sp[B_][S_];   // attention probs

    const int w    = threadIdx.x >> 5;
    const int lane = threadIdx.x & 31;
    const int gw   = blockIdx.x * 8 + w;
    unsigned bar = 0;

    const float4* Wi4 = (const float4*)W_ih;
    const float4* Wh4 = (const float4*)W_hh;
    const float4* E4  = (const float4*)emb;

    for (int t = 0; t < T_; ++t) {
        if (threadIdx.x < B_) tok[threadIdx.x] = trg[threadIdx.x * T_ + t];
        __syncthreads();

        const float4* Hi4 = (const float4*)g_h[t & 1];
        float* __restrict__ h_out = g_h[(t & 1) ^ 1];
        const float4* HH4 = (const float4*)g_hhat;

        // ---- phase 1: LSTM gates + cell update (2048 warp tasks)
        for (int task = gw; task < 2048; task += NW) {
            const int m  = task >> 2;
            const int b0 = (task & 3) << 3;
            int tk[8];
            #pragma unroll
            for (int u = 0; u < 8; ++u) tk[u] = tok[b0 + u];

            float acc[4][8];
            #pragma unroll
            for (int g = 0; g < 4; ++g)
                #pragma unroll
                for (int u = 0; u < 8; ++u) acc[g][u] = 0.f;

            #pragma unroll
            for (int kk = 0; kk < 4; ++kk) {
                const int i = (kk << 5) + lane;
                float4 wv[4];
                #pragma unroll
                for (int g = 0; g < 4; ++g)
                    wv[g] = Wi4[(size_t)(g * H_ + m) * 256 + i];
                #pragma unroll
                for (int u = 0; u < 8; ++u) {
                    float4 xv = E4[(size_t)tk[u] * 128 + i];
                    #pragma unroll
                    for (int g = 0; g < 4; ++g)
                        acc[g][u] += xv.x*wv[g].x + xv.y*wv[g].y
                                   + xv.z*wv[g].z + xv.w*wv[g].w;
                }
            }
            #pragma unroll
            for (int kk = 0; kk < 4; ++kk) {
                const int i = (kk << 5) + lane;
                float4 wv[4];
                #pragma unroll
                for (int g = 0; g < 4; ++g)
                    wv[g] = Wi4[(size_t)(g * H_ + m) * 256 + 128 + i];
                #pragma unroll
                for (int u = 0; u < 8; ++u) {
                    float4 xv = HH4[(b0 + u) * 128 + i];
                    #pragma unroll
                    for (int g = 0; g < 4; ++g)
                        acc[g][u] += xv.x*wv[g].x + xv.y*wv[g].y
                                   + xv.z*wv[g].z + xv.w*wv[g].w;
                }
            }
            #pragma unroll
            for (int kk = 0; kk < 4; ++kk) {
                const int i = (kk << 5) + lane;
                float4 wv[4];
                #pragma unroll
                for (int g = 0; g < 4; ++g)
                    wv[g] = Wh4[(size_t)(g * H_ + m) * 128 + i];
                #pragma unroll
                for (int u = 0; u < 8; ++u) {
                    float4 xv = Hi4[(b0 + u) * 128 + i];
                    #pragma unroll
                    for (int g = 0; g < 4; ++g)
                        acc[g][u] += xv.x*wv[g].x + xv.y*wv[g].y
                                   + xv.z*wv[g].z + xv.w*wv[g].w;
                }
            }
            #pragma unroll
            for (int o = 16; o; o >>= 1)
                #pragma unroll
                for (int g = 0; g < 4; ++g)
                    #pragma unroll
                    for (int u = 0; u < 8; ++u)
                        acc[g][u] += __shfl_xor_sync(0xFFFFFFFFu, acc[g][u], o);

            if (lane < 8) {
                float vi = 0.f, vf = 0.f, vg = 0.f, vo = 0.f;
                #pragma unroll
                for (int u = 0; u < 8; ++u)
                    if (lane == u) { vi = acc[0][u]; vf = acc[1][u];
                                     vg = acc[2][u]; vo = acc[3][u]; }
                const int b = b0 + lane;
                float ig = sigmoidf_(vi + b_ih[m]        + b_hh[m]);
                float fg = sigmoidf_(vf + b_ih[H_ + m]   + b_hh[H_ + m]);
                float gg = tanhf    (vg + b_ih[2*H_ + m] + b_hh[2*H_ + m]);
                float og = sigmoidf_(vo + b_ih[3*H_ + m] + b_hh[3*H_ + m]);
                float cn = fg * g_c[b * H_ + m] + ig * gg;
                g_c[b * H_ + m] = cn;
                h_out[b * H_ + m] = og * tanhf(cn);
            }
        }
        grid_sync(++bar * NB);

        // ---- phase 2: scores[r] = (h[b].Q[r] + qb[r]) * scale (2048 tasks)
        {
            const float4* H4 = (const float4*)h_out;
            for (int r = gw; r < B_ * S_; r += NW) {
                const int b = r >> 6;
                const float4* qv = (const float4*)(g_Q + (size_t)r * H_);
                float a = 0.f;
                #pragma unroll
                for (int i = lane; i < H_ / 4; i += 32) {
                    float4 h4 = H4[b * 128 + i], q4 = qv[i];
                    a += h4.x*q4.x + h4.y*q4.y + h4.z*q4.z + h4.w*q4.w;
                }
                #pragma unroll
                for (int o = 16; o; o >>= 1) a += __shfl_xor_sync(0xFFFFFFFFu, a, o);
                if (lane == 0) g_sc[r] = (a + g_qb[r]) * SCALE_;
            }
        }
        grid_sync(++bar * NB);

        // ---- phase 3: per-block softmax (smem) then h_hat
        {
            // each warp: softmax for 4 batches
            #pragma unroll
            for (int bb = w * 4; bb < w * 4 + 4; ++bb) {
                float v0 = g_sc[bb * S_ + lane], v1 = g_sc[bb * S_ + 32 + lane];
                float mx = fmaxf(v0, v1);
                #pragma unroll
                for (int o = 16; o; o >>= 1)
                    mx = fmaxf(mx, __shfl_xor_sync(0xFFFFFFFFu, mx, o));
                float e0 = __expf(v0 - mx), e1 = __expf(v1 - mx);
                float sm = e0 + e1;
                #pragma unroll
                for (int o = 16; o; o >>= 1) sm += __shfl_xor_sync(0xFFFFFFFFu, sm, o);
                float inv = 1.0f / sm;
                sp[bb][lane] = e0 * inv;
                sp[bb][lane + 32] = e1 * inv;
            }
            __syncthreads();

            const float4* H4 = (const float4*)h_out;
            for (int q = w; q < 16; q += 8) {
                const int j = blockIdx.x + NB * (q >> 2);
                if (j >= H_) continue;
                const int b0 = (q & 3) << 3;
                const float4* Wr = (const float4*)(Wah + (size_t)j * (H_ + SD_));
                float acc[8] = {};
                #pragma unroll
                for (int kk = 0; kk < 4; ++kk) {
                    const int i = (kk << 5) + lane;
                    float4 ww = Wr[i];
                    #pragma unroll
                    for (int u = 0; u < 8; ++u) {
                        float4 a = H4[(b0 + u) * 128 + i];
                        acc[u] += a.x*ww.x + a.y*ww.y + a.z*ww.z + a.w*ww.w;
                    }
                }
                const float* gt = g_GT + (size_t)j * (B_ * S_);
                #pragma unroll
                for (int u = 0; u < 8; ++u) {
                    const int b = b0 + u;
                    float g0 = gt[b * S_ + lane];
                    float g1 = gt[b * S_ + 32 + lane];
                    acc[u] += sp[b][lane] * g0 + sp[b][lane + 32] * g1;
                }
                #pragma unroll
                for (int o = 16; o; o >>= 1)
                    #pragma unroll
                    for (int u = 0; u < 8; ++u)
                        acc[u] += __shfl_xor_sync(0xFFFFFFFFu, acc[u], o);
                if (lane < 8) {
                    float av = 0.f;
                    #pragma unroll
                    for (int u = 0; u < 8; ++u)
                        if (lane == u) av = acc[u];
                    const int b = b0 + lane;
                    float v = tanhf(av + bah[j]);
                    g_hhat[b * H_ + j] = v;
                    g_outs[((size_t)t * B_ + b) * H_ + j] = v;
                }
            }
        }
        grid_sync(++bar * NB);
    }

    // tail: final h, c, h_hat
    size_t base = (size_t)B_ * T_ * V_;
    for (int idx = blockIdx.x * NT + threadIdx.x; idx < B_ * H_; idx += NB * NT) {
        out[base + idx]               = g_h[0][idx];
        out[base + B_ * H_ + idx]     = g_c[idx];
        out[base + 2 * B_ * H_ + idx] = g_hhat[idx];
    }
}

// ---------------- final projection GEMM (fp32 64x64 tile) ----------------
#define BM 64
#define BN 64
#define BK 16
__global__ void __launch_bounds__(256) gemm_kernel(
    const float* __restrict__ Wfc, const float* __restrict__ bfc,
    float* __restrict__ out)
{
    __shared__ float As[BK][BM + 4];
    __shared__ float Bs[BK][BN + 4];

    const int tid = threadIdx.x;
    const int tx = tid & 15, ty = tid >> 4;
    const int r0 = blockIdx.y * BM;
    const int v0 = blockIdx.x * BN;
    const int ld_row = tid >> 2;
    const int ld_k   = (tid & 3) * 4;

    const float* __restrict__ A = g_outs;
    float acc[4][4] = {};

    for (int k0 = 0; k0 < H_; k0 += BK) {
        float4 a  = *(const float4*)&A  [(size_t)(r0 + ld_row) * H_ + k0 + ld_k];
        float4 bb = *(const float4*)&Wfc[(size_t)(v0 + ld_row) * H_ + k0 + ld_k];
        As[ld_k + 0][ld_row] = a.x;  As[ld_k + 1][ld_row] = a.y;
        As[ld_k + 2][ld_row] = a.z;  As[ld_k + 3][ld_row] = a.w;
        Bs[ld_k + 0][ld_row] = bb.x; Bs[ld_k + 1][ld_row] = bb.y;
        Bs[ld_k + 2][ld_row] = bb.z; Bs[ld_k + 3][ld_row] = bb.w;
        __syncthreads();
        #pragma unroll
        for (int k = 0; k < BK; ++k) {
            float4 av = *(const float4*)&As[k][ty * 4];
            float4 bv = *(const float4*)&Bs[k][tx * 4];
            acc[0][0]+=av.x*bv.x; acc[0][1]+=av.x*bv.y; acc[0][2]+=av.x*bv.z; acc[0][3]+=av.x*bv.w;
            acc[1][0]+=av.y*bv.x; acc[1][1]+=av.y*bv.y; acc[1][2]+=av.y*bv.z; acc[1][3]+=av.y*bv.w;
            acc[2][0]+=av.z*bv.x; acc[2][1]+=av.z*bv.y; acc[2][2]+=av.z*bv.z; acc[2][3]+=av.z*bv.w;
            acc[3][0]+=av.w*bv.x; acc[3][1]+=av.w*bv.y; acc[3][2]+=av.w*bv.z; acc[3][3]+=av.w*bv.w;
        }
        __syncthreads();
    }

    const int v = v0 + tx * 4;
    float4 bias = *(const float4*)&bfc[v];
    #pragma unroll
    for (int i = 0; i < 4; ++i) {
        int r = r0 + ty * 4 + i;
        int tt = r >> 5;
        int bb2 = r & 31;
        size_t off = ((size_t)(bb2 * T_ + tt)) * V_ + v;
        float4 res;
        res.x = acc[i][0] + bias.x;
        res.y = acc[i][1] + bias.y;
        res.z = acc[i][2] + bias.z;
        res.w = acc[i][3] + bias.w;
        *(float4*)&out[off] = res;
    }
}

extern "C" void kernel_launch(void* const* d_in, const int* in_sizes, int n_in,
                              void* d_out, int out_size) {
    const float* src    = (const float*)d_in[0];
    const int*   trg    = (const int*)  d_in[1];
    const float* emb    = (const float*)d_in[2];
    const float* W_ih   = (const float*)d_in[3];
    const float* b_ih   = (const float*)d_in[4];
    const float* W_hh   = (const float*)d_in[5];
    const float* b_hh   = (const float*)d_in[6];
    const float* Wp     = (const float*)d_in[7];
    const float* bp     = (const float*)d_in[8];
    const float* Wah    = (const float*)d_in[9];
    const float* bah    = (const float*)d_in[10];
    const float* Wfc    = (const float*)d_in[11];
    const float* bfc    = (const float*)d_in[12];
    const float* iff    = (const float*)d_in[13];
    const float* hinit  = (const float*)d_in[14];
    float* out = (float*)d_out;

    init_kernel<<<32, 512>>>(hinit, iff);
    qb_kernel<<<256, 256>>>(src, bp);
    qgemm_kernel<<<dim3(H_ / PBN, (B_ * S_) / PBM), 256>>>(src, Wp);
    gtgemm_kernel<<<dim3((B_ * S_) / PBN, H_ / PBM), 256>>>(Wah, src);

    step_kernel<<<NB, NT>>>(trg, emb, W_ih, b_ih, W_hh, b_hh,
                            Wah, bah, out);

    dim3 ggrid(V_ / BN, (T_ * B_) / BM);
    gemm_kernel<<<ggrid, 256>>>(Wfc, bfc, out);
}

// round 7
// speedup vs baseline: 3.2311x; 1.3464x over previous
#include <cuda_runtime.h>
#include <cuda_bf16.h>
#include <math.h>
#include <cstdint>

#define B_  32
#define T_  64
#define S_  64
#define V_  32000
#define E_  512
#define H_  512
#define SD_ 1024
#define SCALE_ 0.04419417382415922f  // 1/sqrt(512)

#define NB 148
#define NT 256
#define NW (NB * 8)

__device__ float g_h[2][B_ * H_];
__device__ float g_c[B_ * H_];
__device__ float g_hhat[B_ * H_];
__device__ float g_Q[B_ * S_ * H_];
__device__ float g_GT[H_ * B_ * S_];
__device__ float g_qb[B_ * S_];
__device__ float g_sc[B_ * S_];
__device__ unsigned g_arrive;

// bf16 hi/lo operands for the tensor-core final GEMM
__device__ __nv_bfloat16 g_outs_hi[T_ * B_ * H_];
__device__ __nv_bfloat16 g_outs_lo[T_ * B_ * H_];
__device__ __nv_bfloat16 g_W_hi[(size_t)V_ * H_];
__device__ __nv_bfloat16 g_W_lo[(size_t)V_ * H_];

__device__ __forceinline__ float sigmoidf_(float x) {
    return 1.0f / (1.0f + __expf(-x));
}

__device__ __forceinline__ void grid_sync(unsigned target) {
    __syncthreads();
    if (threadIdx.x == 0) {
        __threadfence();
        atomicAdd(&g_arrive, 1u);
        unsigned v;
        do {
            asm volatile("ld.global.acquire.gpu.u32 %0, [%1];"
                         : "=r"(v) : "l"(&g_arrive));
        } while (v < target);
    }
    __syncthreads();
}

// ---------------- init ----------------
__global__ void init_kernel(const float* __restrict__ hinit,
                            const float* __restrict__ iff) {
    if (blockIdx.x == 0 && threadIdx.x == 0) g_arrive = 0u;
    int idx = blockIdx.x * blockDim.x + threadIdx.x;
    if (idx < B_ * H_) {
        int m = idx & (H_ - 1);
        g_h[0][idx] = hinit[m];
        g_c[idx]    = hinit[H_ + m];
        g_hhat[idx] = iff[m];
    }
}

// ---------------- Wfc -> bf16 hi/lo ----------------
__global__ void __launch_bounds__(256) wconv_kernel(const float* __restrict__ Wfc) {
    const size_t n4 = (size_t)V_ * H_ / 4;
    for (size_t i = blockIdx.x * 256 + threadIdx.x; i < n4; i += (size_t)gridDim.x * 256) {
        float4 wv = ((const float4*)Wfc)[i];
        float w[4] = {wv.x, wv.y, wv.z, wv.w};
        __nv_bfloat16 hi[4], lo[4];
        #pragma unroll
        for (int u = 0; u < 4; ++u) {
            hi[u] = __float2bfloat16(w[u]);
            lo[u] = __float2bfloat16(w[u] - __bfloat162float(hi[u]));
        }
        *(ushort4*)&g_W_hi[i * 4] = make_ushort4(
            __bfloat16_as_ushort(hi[0]), __bfloat16_as_ushort(hi[1]),
            __bfloat16_as_ushort(hi[2]), __bfloat16_as_ushort(hi[3]));
        *(ushort4*)&g_W_lo[i * 4] = make_ushort4(
            __bfloat16_as_ushort(lo[0]), __bfloat16_as_ushort(lo[1]),
            __bfloat16_as_ushort(lo[2]), __bfloat16_as_ushort(lo[3]));
    }
}

// ---------------- qb[r] = bp . src[r] ----------------
__global__ void __launch_bounds__(256) qb_kernel(
    const float* __restrict__ src, const float* __restrict__ bp)
{
    const int w = threadIdx.x >> 5, lane = threadIdx.x & 31;
    const int r = blockIdx.x * 8 + w;
    const float4* sr = (const float4*)(src + (size_t)r * SD_);
    const float4* bv = (const float4*)bp;
    float a = 0.f;
    #pragma unroll
    for (int i = lane; i < SD_ / 4; i += 32) {
        float4 x = sr[i], b = bv[i];
        a += x.x*b.x + x.y*b.y + x.z*b.z + x.w*b.w;
    }
    #pragma unroll
    for (int o = 16; o; o >>= 1) a += __shfl_xor_sync(0xFFFFFFFFu, a, o);
    if (lane == 0) g_qb[r] = a;
}

// ---------------- Q = src @ Wp (NN) ----------------
#define PBM 64
#define PBN 64
#define PBK 16
__global__ void __launch_bounds__(256) qgemm_kernel(
    const float* __restrict__ src, const float* __restrict__ Wp)
{
    __shared__ float As[PBK][PBM + 4];
    __shared__ float Bs[PBK][PBN + 4];
    const int tid = threadIdx.x;
    const int tx = tid & 15, ty = tid >> 4;
    const int r0 = blockIdx.y * PBM;
    const int v0 = blockIdx.x * PBN;
    const int a_row = tid >> 2, a_k = (tid & 3) * 4;
    const int b_k = tid >> 4, b_n = (tid & 15) * 4;

    float acc[4][4] = {};
    for (int k0 = 0; k0 < SD_; k0 += PBK) {
        float4 a = *(const float4*)&src[(size_t)(r0 + a_row) * SD_ + k0 + a_k];
        As[a_k + 0][a_row] = a.x; As[a_k + 1][a_row] = a.y;
        As[a_k + 2][a_row] = a.z; As[a_k + 3][a_row] = a.w;
        *(float4*)&Bs[b_k][b_n] =
            *(const float4*)&Wp[(size_t)(k0 + b_k) * H_ + v0 + b_n];
        __syncthreads();
        #pragma unroll
        for (int k = 0; k < PBK; ++k) {
            float4 av = *(const float4*)&As[k][ty * 4];
            float4 bv = *(const float4*)&Bs[k][tx * 4];
            acc[0][0]+=av.x*bv.x; acc[0][1]+=av.x*bv.y; acc[0][2]+=av.x*bv.z; acc[0][3]+=av.x*bv.w;
            acc[1][0]+=av.y*bv.x; acc[1][1]+=av.y*bv.y; acc[1][2]+=av.y*bv.z; acc[1][3]+=av.y*bv.w;
            acc[2][0]+=av.z*bv.x; acc[2][1]+=av.z*bv.y; acc[2][2]+=av.z*bv.z; acc[2][3]+=av.z*bv.w;
            acc[3][0]+=av.w*bv.x; acc[3][1]+=av.w*bv.y; acc[3][2]+=av.w*bv.z; acc[3][3]+=av.w*bv.w;
        }
        __syncthreads();
    }
    #pragma unroll
    for (int i = 0; i < 4; ++i) {
        float4 res = make_float4(acc[i][0], acc[i][1], acc[i][2], acc[i][3]);
        *(float4*)&g_Q[(size_t)(r0 + ty * 4 + i) * H_ + v0 + tx * 4] = res;
    }
}

// ---------------- GT[j][r] = Wah[j,512:1536] . src[r] (NT) ----------------
__global__ void __launch_bounds__(256) gtgemm_kernel(
    const float* __restrict__ Wah, const float* __restrict__ src)
{
    __shared__ float As[PBK][PBM + 4];
    __shared__ float Bs[PBK][PBN + 4];
    const int tid = threadIdx.x;
    const int tx = tid & 15, ty = tid >> 4;
    const int j0 = blockIdx.y * PBM;
    const int r0 = blockIdx.x * PBN;
    const int ld_row = tid >> 2, ld_k = (tid & 3) * 4;

    float acc[4][4] = {};
    for (int k0 = 0; k0 < SD_; k0 += PBK) {
        float4 a = *(const float4*)&Wah[(size_t)(j0 + ld_row) * (H_ + SD_) + H_ + k0 + ld_k];
        float4 b = *(const float4*)&src[(size_t)(r0 + ld_row) * SD_ + k0 + ld_k];
        As[ld_k + 0][ld_row] = a.x; As[ld_k + 1][ld_row] = a.y;
        As[ld_k + 2][ld_row] = a.z; As[ld_k + 3][ld_row] = a.w;
        Bs[ld_k + 0][ld_row] = b.x; Bs[ld_k + 1][ld_row] = b.y;
        Bs[ld_k + 2][ld_row] = b.z; Bs[ld_k + 3][ld_row] = b.w;
        __syncthreads();
        #pragma unroll
        for (int k = 0; k < PBK; ++k) {
            float4 av = *(const float4*)&As[k][ty * 4];
            float4 bv = *(const float4*)&Bs[k][tx * 4];
            acc[0][0]+=av.x*bv.x; acc[0][1]+=av.x*bv.y; acc[0][2]+=av.x*bv.z; acc[0][3]+=av.x*bv.w;
            acc[1][0]+=av.y*bv.x; acc[1][1]+=av.y*bv.y; acc[1][2]+=av.y*bv.z; acc[1][3]+=av.y*bv.w;
            acc[2][0]+=av.z*bv.x; acc[2][1]+=av.z*bv.y; acc[2][2]+=av.z*bv.z; acc[2][3]+=av.z*bv.w;
            acc[3][0]+=av.w*bv.x; acc[3][1]+=av.w*bv.y; acc[3][2]+=av.w*bv.z; acc[3][3]+=av.w*bv.w;
        }
        __syncthreads();
    }
    #pragma unroll
    for (int i = 0; i < 4; ++i) {
        float4 res = make_float4(acc[i][0], acc[i][1], acc[i][2], acc[i][3]);
        *(float4*)&g_GT[(size_t)(j0 + ty * 4 + i) * (B_ * S_) + r0 + tx * 4] = res;
    }
}

// ================= persistent recurrence kernel =================
__global__ void __launch_bounds__(NT) step_kernel(
    const int* __restrict__ trg, const float* __restrict__ emb,
    const float* __restrict__ W_ih, const float* __restrict__ b_ih,
    const float* __restrict__ W_hh, const float* __restrict__ b_hh,
    const float* __restrict__ Wah, const float* __restrict__ bah,
    float* __restrict__ out)
{
    __shared__ int   tok[B_];
    __shared__ float sp[B_][S_];

    const int w    = threadIdx.x >> 5;
    const int lane = threadIdx.x & 31;
    const int gw   = blockIdx.x * 8 + w;
    unsigned bar = 0;

    const float4* Wi4 = (const float4*)W_ih;
    const float4* Wh4 = (const float4*)W_hh;
    const float4* E4  = (const float4*)emb;

    for (int t = 0; t < T_; ++t) {
        if (threadIdx.x < B_) tok[threadIdx.x] = trg[threadIdx.x * T_ + t];
        __syncthreads();

        const float4* Hi4 = (const float4*)g_h[t & 1];
        float* __restrict__ h_out = g_h[(t & 1) ^ 1];
        const float4* HH4 = (const float4*)g_hhat;

        // phase 1: LSTM gates + cell update
        for (int task = gw; task < 2048; task += NW) {
            const int m  = task >> 2;
            const int b0 = (task & 3) << 3;
            int tk[8];
            #pragma unroll
            for (int u = 0; u < 8; ++u) tk[u] = tok[b0 + u];

            float acc[4][8];
            #pragma unroll
            for (int g = 0; g < 4; ++g)
                #pragma unroll
                for (int u = 0; u < 8; ++u) acc[g][u] = 0.f;

            #pragma unroll
            for (int kk = 0; kk < 4; ++kk) {
                const int i = (kk << 5) + lane;
                float4 wv[4];
                #pragma unroll
                for (int g = 0; g < 4; ++g)
                    wv[g] = Wi4[(size_t)(g * H_ + m) * 256 + i];
                #pragma unroll
                for (int u = 0; u < 8; ++u) {
                    float4 xv = E4[(size_t)tk[u] * 128 + i];
                    #pragma unroll
                    for (int g = 0; g < 4; ++g)
                        acc[g][u] += xv.x*wv[g].x + xv.y*wv[g].y
                                   + xv.z*wv[g].z + xv.w*wv[g].w;
                }
            }
            #pragma unroll
            for (int kk = 0; kk < 4; ++kk) {
                const int i = (kk << 5) + lane;
                float4 wv[4];
                #pragma unroll
                for (int g = 0; g < 4; ++g)
                    wv[g] = Wi4[(size_t)(g * H_ + m) * 256 + 128 + i];
                #pragma unroll
                for (int u = 0; u < 8; ++u) {
                    float4 xv = HH4[(b0 + u) * 128 + i];
                    #pragma unroll
                    for (int g = 0; g < 4; ++g)
                        acc[g][u] += xv.x*wv[g].x + xv.y*wv[g].y
                                   + xv.z*wv[g].z + xv.w*wv[g].w;
                }
            }
            #pragma unroll
            for (int kk = 0; kk < 4; ++kk) {
                const int i = (kk << 5) + lane;
                float4 wv[4];
                #pragma unroll
                for (int g = 0; g < 4; ++g)
                    wv[g] = Wh4[(size_t)(g * H_ + m) * 128 + i];
                #pragma unroll
                for (int u = 0; u < 8; ++u) {
                    float4 xv = Hi4[(b0 + u) * 128 + i];
                    #pragma unroll
                    for (int g = 0; g < 4; ++g)
                        acc[g][u] += xv.x*wv[g].x + xv.y*wv[g].y
                                   + xv.z*wv[g].z + xv.w*wv[g].w;
                }
            }
            #pragma unroll
            for (int o = 16; o; o >>= 1)
                #pragma unroll
                for (int g = 0; g < 4; ++g)
                    #pragma unroll
                    for (int u = 0; u < 8; ++u)
                        acc[g][u] += __shfl_xor_sync(0xFFFFFFFFu, acc[g][u], o);

            if (lane < 8) {
                float vi = 0.f, vf = 0.f, vg = 0.f, vo = 0.f;
                #pragma unroll
                for (int u = 0; u < 8; ++u)
                    if (lane == u) { vi = acc[0][u]; vf = acc[1][u];
                                     vg = acc[2][u]; vo = acc[3][u]; }
                const int b = b0 + lane;
                float ig = sigmoidf_(vi + b_ih[m]        + b_hh[m]);
                float fg = sigmoidf_(vf + b_ih[H_ + m]   + b_hh[H_ + m]);
                float gg = tanhf    (vg + b_ih[2*H_ + m] + b_hh[2*H_ + m]);
                float og = sigmoidf_(vo + b_ih[3*H_ + m] + b_hh[3*H_ + m]);
                float cn = fg * g_c[b * H_ + m] + ig * gg;
                g_c[b * H_ + m] = cn;
                h_out[b * H_ + m] = og * tanhf(cn);
            }
        }
        grid_sync(++bar * NB);

        // phase 2: scores
        {
            const float4* H4 = (const float4*)h_out;
            for (int r = gw; r < B_ * S_; r += NW) {
                const int b = r >> 6;
                const float4* qv = (const float4*)(g_Q + (size_t)r * H_);
                float a = 0.f;
                #pragma unroll
                for (int i = lane; i < H_ / 4; i += 32) {
                    float4 h4 = H4[b * 128 + i], q4 = qv[i];
                    a += h4.x*q4.x + h4.y*q4.y + h4.z*q4.z + h4.w*q4.w;
                }
                #pragma unroll
                for (int o = 16; o; o >>= 1) a += __shfl_xor_sync(0xFFFFFFFFu, a, o);
                if (lane == 0) g_sc[r] = (a + g_qb[r]) * SCALE_;
            }
        }
        grid_sync(++bar * NB);

        // phase 3: softmax + h_hat (+ bf16 hi/lo emit for final GEMM)
        {
            #pragma unroll
            for (int bb = w * 4; bb < w * 4 + 4; ++bb) {
                float v0 = g_sc[bb * S_ + lane], v1 = g_sc[bb * S_ + 32 + lane];
                float mx = fmaxf(v0, v1);
                #pragma unroll
                for (int o = 16; o; o >>= 1)
                    mx = fmaxf(mx, __shfl_xor_sync(0xFFFFFFFFu, mx, o));
                float e0 = __expf(v0 - mx), e1 = __expf(v1 - mx);
                float sm = e0 + e1;
                #pragma unroll
                for (int o = 16; o; o >>= 1) sm += __shfl_xor_sync(0xFFFFFFFFu, sm, o);
                float inv = 1.0f / sm;
                sp[bb][lane] = e0 * inv;
                sp[bb][lane + 32] = e1 * inv;
            }
            __syncthreads();

            const float4* H4 = (const float4*)h_out;
            for (int q = w; q < 16; q += 8) {
                const int j = blockIdx.x + NB * (q >> 2);
                if (j >= H_) continue;
                const int b0 = (q & 3) << 3;
                const float4* Wr = (const float4*)(Wah + (size_t)j * (H_ + SD_));
                float acc[8] = {};
                #pragma unroll
                for (int kk = 0; kk < 4; ++kk) {
                    const int i = (kk << 5) + lane;
                    float4 ww = Wr[i];
                    #pragma unroll
                    for (int u = 0; u < 8; ++u) {
                        float4 a = H4[(b0 + u) * 128 + i];
                        acc[u] += a.x*ww.x + a.y*ww.y + a.z*ww.z + a.w*ww.w;
                    }
                }
                const float* gt = g_GT + (size_t)j * (B_ * S_);
                #pragma unroll
                for (int u = 0; u < 8; ++u) {
                    const int b = b0 + u;
                    float g0 = gt[b * S_ + lane];
                    float g1 = gt[b * S_ + 32 + lane];
                    acc[u] += sp[b][lane] * g0 + sp[b][lane + 32] * g1;
                }
                #pragma unroll
                for (int o = 16; o; o >>= 1)
                    #pragma unroll
                    for (int u = 0; u < 8; ++u)
                        acc[u] += __shfl_xor_sync(0xFFFFFFFFu, acc[u], o);
                if (lane < 8) {
                    float av = 0.f;
                    #pragma unroll
                    for (int u = 0; u < 8; ++u)
                        if (lane == u) av = acc[u];
                    const int b = b0 + lane;
                    float v = tanhf(av + bah[j]);
                    g_hhat[b * H_ + j] = v;
                    size_t oidx = ((size_t)t * B_ + b) * H_ + j;
                    __nv_bfloat16 hi = __float2bfloat16(v);
                    g_outs_hi[oidx] = hi;
                    g_outs_lo[oidx] = __float2bfloat16(v - __bfloat162float(hi));
                }
            }
        }
        grid_sync(++bar * NB);
    }

    size_t base = (size_t)B_ * T_ * V_;
    for (int idx = blockIdx.x * NT + threadIdx.x; idx < B_ * H_; idx += NB * NT) {
        out[base + idx]               = g_h[0][idx];
        out[base + B_ * H_ + idx]     = g_c[idx];
        out[base + 2 * B_ * H_ + idx] = g_hhat[idx];
    }
}

// ================= final GEMM: bf16 hi/lo on tensor cores =================
// C[r][v] = sum_h A[r][h] * W[v][h]; A=outs(2048x512), W=Wfc(32000x512)
// block 128(M)x128(N), 8 warps 4x2 -> warp 32x64; mma.m16n8k16.bf16
#define GPAD 40   // 32 k + 8 pad bf16 per smem row (80B stride, conflict-free)
__global__ void __launch_bounds__(256) fgemm_kernel(
    const float* __restrict__ bfc, float* __restrict__ out)
{
    __shared__ __nv_bfloat16 As[2][128][GPAD];  // [hi/lo][m][k]
    __shared__ __nv_bfloat16 Bs[2][128][GPAD];  // [hi/lo][n][k]

    const int tid  = threadIdx.x;
    const int w    = tid >> 5;
    const int lane = tid & 31;
    const int r0 = blockIdx.y * 128;
    const int v0 = blockIdx.x * 128;
    const int wm0 = (w >> 1) * 32;       // warp m offset
    const int wn0 = (w & 1) * 64;        // warp n offset

    float acc[2][8][4];
    #pragma unroll
    for (int mt = 0; mt < 2; ++mt)
        #pragma unroll
        for (int nt = 0; nt < 8; ++nt)
            #pragma unroll
            for (int i = 0; i < 4; ++i) acc[mt][nt][i] = 0.f;

    for (int k0 = 0; k0 < H_; k0 += 32) {
        __syncthreads();
        // stage A hi/lo and B hi/lo: each 128 rows x 32 bf16 = 512 uint4
        #pragma unroll
        for (int it = 0; it < 2; ++it) {
            int idx = it * 256 + tid;
            int row = idx >> 2, q = idx & 3;
            *(uint4*)&As[0][row][q * 8] =
                ((const uint4*)(g_outs_hi + (size_t)(r0 + row) * H_ + k0))[q];
            *(uint4*)&As[1][row][q * 8] =
                ((const uint4*)(g_outs_lo + (size_t)(r0 + row) * H_ + k0))[q];
            *(uint4*)&Bs[0][row][q * 8] =
                ((const uint4*)(g_W_hi + (size_t)(v0 + row) * H_ + k0))[q];
            *(uint4*)&Bs[1][row][q * 8] =
                ((const uint4*)(g_W_lo + (size_t)(v0 + row) * H_ + k0))[q];
        }
        __syncthreads();

        #pragma unroll
        for (int ks = 0; ks < 32; ks += 16) {
            // load A fragments (hi, lo): ldmatrix.x4 per mtile per kind
            uint32_t afr[2][2][4];   // [kind][mtile][reg]
            const int sec = lane >> 3;
            #pragma unroll
            for (int kind = 0; kind < 2; ++kind)
                #pragma unroll
                for (int mt = 0; mt < 2; ++mt) {
                    uint32_t addr = (uint32_t)__cvta_generic_to_shared(
                        &As[kind][wm0 + mt * 16 + (sec & 1) * 8 + (lane & 7)]
                           [ks + (sec >> 1) * 8]);
                    asm volatile(
                        "ldmatrix.sync.aligned.m8n8.x4.shared.b16 {%0,%1,%2,%3}, [%4];"
                        : "=r"(afr[kind][mt][0]), "=r"(afr[kind][mt][1]),
                          "=r"(afr[kind][mt][2]), "=r"(afr[kind][mt][3])
                        : "r"(addr));
                }
            // load B fragments: x4 covers two n8 tiles
            uint32_t bfr[2][8][2];   // [kind][ntile][reg]
            #pragma unroll
            for (int kind = 0; kind < 2; ++kind)
                #pragma unroll
                for (int p = 0; p < 4; ++p) {
                    uint32_t addr = (uint32_t)__cvta_generic_to_shared(
                        &Bs[kind][wn0 + p * 16 + (sec >> 1) * 8 + (lane & 7)]
                           [ks + (sec & 1) * 8]);
                    asm volatile(
                        "ldmatrix.sync.aligned.m8n8.x4.shared.b16 {%0,%1,%2,%3}, [%4];"
                        : "=r"(bfr[kind][p*2][0]), "=r"(bfr[kind][p*2][1]),
                          "=r"(bfr[kind][p*2+1][0]), "=r"(bfr[kind][p*2+1][1])
                        : "r"(addr));
                }
            // mma: Ahi*Bhi + Ahi*Blo + Alo*Bhi
            #pragma unroll
            for (int mt = 0; mt < 2; ++mt)
                #pragma unroll
                for (int nt = 0; nt < 8; ++nt) {
                    #pragma unroll
                    for (int pr = 0; pr < 3; ++pr) {
                        const int ak = (pr == 2) ? 1 : 0;
                        const int bk = (pr == 1) ? 1 : 0;
                        asm volatile(
                            "mma.sync.aligned.m16n8k16.row.col.f32.bf16.bf16.f32 "
                            "{%0,%1,%2,%3}, {%4,%5,%6,%7}, {%8,%9}, {%0,%1,%2,%3};"
                            : "+f"(acc[mt][nt][0]), "+f"(acc[mt][nt][1]),
                              "+f"(acc[mt][nt][2]), "+f"(acc[mt][nt][3])
                            : "r"(afr[ak][mt][0]), "r"(afr[ak][mt][1]),
                              "r"(afr[ak][mt][2]), "r"(afr[ak][mt][3]),
                              "r"(bfr[bk][nt][0]), "r"(bfr[bk][nt][1]));
                    }
                }
        }
    }

    // epilogue: scatter out[(b*T+t)*V + v] with bias
    #pragma unroll
    for (int mt = 0; mt < 2; ++mt) {
        #pragma unroll
        for (int half = 0; half < 2; ++half) {
            int r = r0 + wm0 + mt * 16 + (lane >> 2) + half * 8;
            int tt = r >> 5, bb = r & 31;
            size_t rowoff = ((size_t)(bb * T_ + tt)) * V_;
            #pragma unroll
            for (int nt = 0; nt < 8; ++nt) {
                int v = v0 + wn0 + nt * 8 + (lane & 3) * 2;
                float2 res;
                res.x = acc[mt][nt][half * 2 + 0] + bfc[v];
                res.y = acc[mt][nt][half * 2 + 1] + bfc[v + 1];
                *(float2*)&out[rowoff + v] = res;
            }
        }
    }
}

extern "C" void kernel_launch(void* const* d_in, const int* in_sizes, int n_in,
                              void* d_out, int out_size) {
    const float* src    = (const float*)d_in[0];
    const int*   trg    = (const int*)  d_in[1];
    const float* emb    = (const float*)d_in[2];
    const float* W_ih   = (const float*)d_in[3];
    const float* b_ih   = (const float*)d_in[4];
    const float* W_hh   = (const float*)d_in[5];
    const float* b_hh   = (const float*)d_in[6];
    const float* Wp     = (const float*)d_in[7];
    const float* bp     = (const float*)d_in[8];
    const float* Wah    = (const float*)d_in[9];
    const float* bah    = (const float*)d_in[10];
    const float* Wfc    = (const float*)d_in[11];
    const float* bfc    = (const float*)d_in[12];
    const float* iff    = (const float*)d_in[13];
    const float* hinit  = (const float*)d_in[14];
    float* out = (float*)d_out;

    init_kernel<<<32, 512>>>(hinit, iff);
    wconv_kernel<<<2048, 256>>>(Wfc);
    qb_kernel<<<256, 256>>>(src, bp);
    qgemm_kernel<<<dim3(H_ / PBN, (B_ * S_) / PBM), 256>>>(src, Wp);
    gtgemm_kernel<<<dim3((B_ * S_) / PBN, H_ / PBM), 256>>>(Wah, src);

    step_kernel<<<NB, NT>>>(trg, emb, W_ih, b_ih, W_hh, b_hh,
                            Wah, bah, out);

    fgemm_kernel<<<dim3(V_ / 128, (T_ * B_) / 128), 256>>>(bfc, out);
}